// round 1
// baseline (speedup 1.0000x reference)
#include <cuda_runtime.h>
#include <math.h>
#include <stdint.h>

// Problem dims
#define B_  2
#define T_  2048
#define E_  1024
#define H_  16
#define D_  64
#define MROWS (B_*T_)            // 4096
#define EP1   (E_+1)             // 1025
#define QKVN  (3*E_)             // 3072
#define AOW   (H_*(D_+1))        // 1040
#define MEXP  (4*E_+3)           // 4099
#define MSHK  (4*(E_+1))         // 4100

// ---------------- scratch (static device globals; no allocation) -------------
__device__ float g_l1 [MROWS*EP1];
__device__ float g_qkv[MROWS*QKVN];
__device__ float g_Q  [B_*H_*T_*D_];
__device__ float g_Kr [B_*H_*T_*D_];
__device__ float g_qt [B_*H_*T_];
__device__ float g_kt [B_*H_*T_];
__device__ float g_v0 [B_*H_*T_];
__device__ float g_o  [MROWS*AOW];
__device__ float g_ap [MROWS*E_];
__device__ float g_y1 [MROWS*E_];
__device__ float g_l2 [MROWS*EP1];
__device__ float g_h  [MROWS*MEXP];
__device__ float g_hp [MROWS*MSHK];
__device__ float g_m  [MROWS*E_];

// ---------------- helpers ----------------------------------------------------
__device__ __forceinline__ float block_reduce_sum(float v, float* red) {
    int tid = threadIdx.x;
    #pragma unroll
    for (int o = 16; o; o >>= 1) v += __shfl_xor_sync(0xffffffffu, v, o);
    if ((tid & 31) == 0) red[tid >> 5] = v;
    __syncthreads();
    float r = (tid < (int)(blockDim.x >> 5)) ? red[tid] : 0.f;
    if (tid < 32) {
        #pragma unroll
        for (int o = 16; o; o >>= 1) r += __shfl_xor_sync(0xffffffffu, r, o);
        if (tid == 0) red[0] = r;
    }
    __syncthreads();
    float out = red[0];
    __syncthreads();
    return out;
}

// ---------------- kernel 1: LN + project of x  -> l1 (M,1025) -----------------
__global__ void ln_project_kernel(const float* __restrict__ x,
                                  const float* __restrict__ lnw,
                                  const float* __restrict__ lnb,
                                  const float* __restrict__ bc,
                                  float* __restrict__ out) {
    int row = blockIdx.x;
    int tid = threadIdx.x;
    const float* xr = x + (size_t)row * E_;
    __shared__ float red[32];
    float loc[4];
    float s = 0.f;
    #pragma unroll
    for (int u = 0; u < 4; ++u) { loc[u] = xr[tid + u * 256]; s += loc[u]; }
    float mean = block_reduce_sum(s, red) * (1.0f / E_);
    float vs = 0.f;
    #pragma unroll
    for (int u = 0; u < 4; ++u) { float d = loc[u] - mean; vs += d * d; }
    float var = block_reduce_sum(vs, red) * (1.0f / E_);
    float rstd = rsqrtf(var + 1e-5f);
    float Kb = expf(bc[0]);
    float ss = 0.f;
    float* orow = out + (size_t)row * EP1;
    #pragma unroll
    for (int u = 0; u < 4; ++u) {
        int c = tid + u * 256;
        float y = (loc[u] - mean) * rstd * lnw[c] + lnb[c];
        orow[1 + c] = y;
        ss += y * y;
    }
    float sst = block_reduce_sum(ss, red);
    if (tid == 0) orow[0] = sqrtf(Kb + sst);
}

// ---------------- generic tiled SGEMM: C = A(M,K) @ W(K,N) + bias ------------
__global__ void __launch_bounds__(256) sgemm_kernel(
        const float* __restrict__ A, const float* __restrict__ W,
        const float* __restrict__ bias, float* __restrict__ C,
        int Mdim, int Ndim, int Kdim) {
    __shared__ float As[8][128];
    __shared__ float Ws[8][128];
    int tid = threadIdx.x;
    int tx = tid & 15, ty = tid >> 4;
    int row0 = blockIdx.y * 128, col0 = blockIdx.x * 128;
    float acc[8][8];
    #pragma unroll
    for (int i = 0; i < 8; ++i)
        #pragma unroll
        for (int j = 0; j < 8; ++j) acc[i][j] = 0.f;

    for (int k0 = 0; k0 < Kdim; k0 += 8) {
        #pragma unroll
        for (int u = 0; u < 4; ++u) {
            int id = tid + u * 256;
            int m = id >> 3, kk = id & 7;
            int gk = k0 + kk;
            As[kk][m] = (gk < Kdim) ? A[(size_t)(row0 + m) * Kdim + gk] : 0.f;
        }
        #pragma unroll
        for (int u = 0; u < 4; ++u) {
            int id = tid + u * 256;
            int kk = id >> 7, n = id & 127;
            int gk = k0 + kk, gn = col0 + n;
            Ws[kk][n] = (gk < Kdim && gn < Ndim) ? W[(size_t)gk * Ndim + gn] : 0.f;
        }
        __syncthreads();
        #pragma unroll
        for (int kk = 0; kk < 8; ++kk) {
            float4 a0 = *(const float4*)&As[kk][ty * 4];
            float4 a1 = *(const float4*)&As[kk][64 + ty * 4];
            float4 b0 = *(const float4*)&Ws[kk][tx * 4];
            float4 b1 = *(const float4*)&Ws[kk][64 + tx * 4];
            float a[8] = {a0.x, a0.y, a0.z, a0.w, a1.x, a1.y, a1.z, a1.w};
            float bb[8] = {b0.x, b0.y, b0.z, b0.w, b1.x, b1.y, b1.z, b1.w};
            #pragma unroll
            for (int i = 0; i < 8; ++i)
                #pragma unroll
                for (int j = 0; j < 8; ++j) acc[i][j] += a[i] * bb[j];
        }
        __syncthreads();
    }
    #pragma unroll
    for (int i = 0; i < 8; ++i) {
        int r = row0 + ((i < 4) ? (ty * 4 + i) : (64 + ty * 4 + (i - 4)));
        #pragma unroll
        for (int j = 0; j < 8; ++j) {
            int c = col0 + ((j < 4) ? (tx * 4 + j) : (64 + tx * 4 + (j - 4)));
            if (c < Ndim) {
                float v = acc[i][j];
                if (bias) v += bias[c];
                C[(size_t)r * Ndim + c] = v;
            }
        }
    }
}

// ---------------- kernel 3: RoPE + per-head norms ----------------------------
// 32 lanes per (bh,t) row, 8 rows per block.
__global__ void rope_prep_kernel(const float* __restrict__ curv) {
    int tid = threadIdx.x;
    int lane = tid & 31;
    int rsub = tid >> 5;
    int r = blockIdx.x * 8 + rsub;            // r = bh*T + t
    int bh = r >> 11;
    int t  = r & (T_ - 1);
    int b  = bh >> 4;
    int h  = bh & 15;
    float Ka = expf(curv[h]);
    size_t base = ((size_t)(b * T_ + t)) * QKVN + h * D_;
    float q1 = g_qkv[base + lane],        q2 = g_qkv[base + 32 + lane];
    float k1 = g_qkv[base + E_ + lane],   k2 = g_qkv[base + E_ + 32 + lane];
    float v1 = g_qkv[base + 2*E_ + lane], v2 = g_qkv[base + 2*E_ + 32 + lane];
    float inv = powf(10000.0f, -(float)lane * (1.0f / 32.0f));
    float fr = (float)t * inv;
    float sn, cs;
    sincosf(fr, &sn, &cs);
    float qa = q1 * cs + q2 * sn, qb = -q1 * sn + q2 * cs;
    float ka = k1 * cs + k2 * sn, kb = -k1 * sn + k2 * cs;
    float sq = qa * qa + qb * qb;
    float sk = ka * ka + kb * kb;
    float sv = v1 * v1 + v2 * v2;
    #pragma unroll
    for (int o = 16; o; o >>= 1) {
        sq += __shfl_xor_sync(0xffffffffu, sq, o);
        sk += __shfl_xor_sync(0xffffffffu, sk, o);
        sv += __shfl_xor_sync(0xffffffffu, sv, o);
    }
    size_t ob = ((size_t)bh * T_ + t) * D_;
    g_Q[ob + lane] = qa;  g_Q[ob + 32 + lane] = qb;
    g_Kr[ob + lane] = ka; g_Kr[ob + 32 + lane] = kb;
    if (lane == 0) {
        g_qt[r] = sqrtf(Ka + sq);
        g_kt[r] = sqrtf(Ka + sk);
        g_v0[r] = sqrtf(Ka + sv);
    }
}

// ---------------- kernel 4: hyperbolic causal attention ----------------------
// One thread owns one query row (q in regs). Key/value tiles of 32 in SMEM.
// No running-max: scores w<=0 with diagonal ~0, so exp(w) in (0,1], ssum>=~1.
__global__ void __launch_bounds__(128) attn_kernel(const float* __restrict__ curv) {
    int bh = blockIdx.y;
    int b = bh >> 4, h = bh & 15;
    int q0 = blockIdx.x * 128;
    int tid = threadIdx.x;
    int qi = q0 + tid;
    float Ka = expf(curv[h]);
    float sK = sqrtf(Ka);
    float rKa = 1.0f / Ka;

    __shared__ float ksh[32 * 64];
    __shared__ float vsh[32 * 64];
    __shared__ float kts[32], v0s[32];

    float q[64];
    {
        const float4* Qb = (const float4*)(g_Q + ((size_t)bh * T_ + qi) * D_);
        #pragma unroll
        for (int d4 = 0; d4 < 16; ++d4) {
            float4 f = Qb[d4];
            q[4*d4] = f.x; q[4*d4+1] = f.y; q[4*d4+2] = f.z; q[4*d4+3] = f.w;
        }
    }
    float myqt = g_qt[(size_t)bh * T_ + qi];
    float o[65];
    #pragma unroll
    for (int e = 0; e < 65; ++e) o[e] = 0.f;
    float ssum = 0.f;

    int kend = q0 + 128;
    for (int k0 = 0; k0 < kend; k0 += 32) {
        __syncthreads();
        #pragma unroll
        for (int u = 0; u < 4; ++u) {
            int idx = tid + u * 128;           // float4 index, 0..511
            int r = idx >> 4, d4 = idx & 15;
            ((float4*)ksh)[idx] =
                ((const float4*)(g_Kr + ((size_t)bh * T_ + k0 + r) * D_))[d4];
            ((float4*)vsh)[idx] =
                ((const float4*)(g_qkv + ((size_t)(b * T_ + k0 + r)) * QKVN + 2*E_ + h * D_))[d4];
        }
        if (tid < 32) {
            kts[tid] = g_kt[(size_t)bh * T_ + k0 + tid];
            v0s[tid] = g_v0[(size_t)bh * T_ + k0 + tid];
        }
        __syncthreads();
        if (qi >= k0) {
            int nk = min(32, qi - k0 + 1);
            for (int j = 0; j < nk; ++j) {
                const float4* kr4 = (const float4*)(ksh + j * 64);
                float d0 = 0.f, d1 = 0.f, d2 = 0.f, d3 = 0.f;
                #pragma unroll
                for (int d4 = 0; d4 < 16; ++d4) {
                    float4 kf = kr4[d4];
                    d0 += q[4*d4]   * kf.x;
                    d1 += q[4*d4+1] * kf.y;
                    d2 += q[4*d4+2] * kf.z;
                    d3 += q[4*d4+3] * kf.w;
                }
                float inner = (d0 + d1) + (d2 + d3) - myqt * kts[j];
                float ratio = fmaxf(-inner * rKa, 1.0f + 1e-7f);
                float dis = sK * acoshf(ratio);
                float p = expf(-dis);
                ssum += p;
                o[0] += p * v0s[j];
                const float4* vr4 = (const float4*)(vsh + j * 64);
                #pragma unroll
                for (int d4 = 0; d4 < 16; ++d4) {
                    float4 vf = vr4[d4];
                    o[1 + 4*d4]     += p * vf.x;
                    o[1 + 4*d4 + 1] += p * vf.y;
                    o[1 + 4*d4 + 2] += p * vf.z;
                    o[1 + 4*d4 + 3] += p * vf.w;
                }
            }
        }
    }
    float rs = 1.0f / ssum;
    #pragma unroll
    for (int e = 0; e < 65; ++e) o[e] *= rs;
    float s2 = 0.f;
    #pragma unroll
    for (int d = 0; d < 64; ++d) s2 += o[1 + d] * o[1 + d];
    float ln2 = o[0] * o[0] - s2;
    float hn = sqrtf(fmaxf(ln2, 1e-12f));
    float sc = sK / hn;
    float* ob = g_o + ((size_t)(b * T_ + qi)) * AOW + h * 65;
    #pragma unroll
    for (int e = 0; e < 65; ++e) ob[e] = o[e] * sc;
}

// ---------------- kernel 6: residual + LN + project -> y1, l2 ----------------
__global__ void resid_ln_project_kernel(const float* __restrict__ x,
                                        const float* __restrict__ lnw,
                                        const float* __restrict__ lnb,
                                        const float* __restrict__ bc) {
    int row = blockIdx.x;
    int tid = threadIdx.x;
    const float* xr = x + (size_t)row * E_;
    const float* ar = g_ap + (size_t)row * E_;
    float* yr = g_y1 + (size_t)row * E_;
    __shared__ float red[32];
    float loc[4];
    float s = 0.f;
    #pragma unroll
    for (int u = 0; u < 4; ++u) {
        int c = tid + u * 256;
        float y = xr[c] + ar[c];
        yr[c] = y;
        loc[u] = y;
        s += y;
    }
    float mean = block_reduce_sum(s, red) * (1.0f / E_);
    float vs = 0.f;
    #pragma unroll
    for (int u = 0; u < 4; ++u) { float d = loc[u] - mean; vs += d * d; }
    float var = block_reduce_sum(vs, red) * (1.0f / E_);
    float rstd = rsqrtf(var + 1e-5f);
    float Kb = expf(bc[0]);
    float ss = 0.f;
    float* orow = g_l2 + (size_t)row * EP1;
    #pragma unroll
    for (int u = 0; u < 4; ++u) {
        int c = tid + u * 256;
        float y = (loc[u] - mean) * rstd * lnw[c] + lnb[c];
        orow[1 + c] = y;
        ss += y * y;
    }
    float sst = block_reduce_sum(ss, red);
    if (tid == 0) orow[0] = sqrtf(Kb + sst);
}

// ---------------- kernel 8: exact GELU + project (mlp curvature) -------------
__global__ void gelu_project_kernel(const float* __restrict__ mc) {
    int row = blockIdx.x;
    int tid = threadIdx.x;
    const float* hr = g_h + (size_t)row * MEXP;
    float* op = g_hp + (size_t)row * MSHK;
    __shared__ float red[32];
    float Km = expf(mc[0]);
    float ss = 0.f;
    for (int c = tid; c < MEXP; c += 256) {
        float v = hr[c];
        float g = 0.5f * v * (1.0f + erff(v * 0.70710678118654752f));
        op[1 + c] = g;
        ss += g * g;
    }
    float sst = block_reduce_sum(ss, red);
    if (tid == 0) op[0] = sqrtf(Km + sst);
}

// ---------------- kernel 10: final residual + project -> out -----------------
__global__ void final_project_kernel(const float* __restrict__ bc,
                                     float* __restrict__ out) {
    int row = blockIdx.x;
    int tid = threadIdx.x;
    const float* yr = g_y1 + (size_t)row * E_;
    const float* mr = g_m + (size_t)row * E_;
    float* orow = out + (size_t)row * EP1;
    __shared__ float red[32];
    float Kb = expf(bc[0]);
    float ss = 0.f;
    #pragma unroll
    for (int u = 0; u < 4; ++u) {
        int c = tid + u * 256;
        float y = yr[c] + mr[c];
        orow[1 + c] = y;
        ss += y * y;
    }
    float sst = block_reduce_sum(ss, red);
    if (tid == 0) orow[0] = sqrtf(Kb + sst);
}

// ---------------- launch -----------------------------------------------------
extern "C" void kernel_launch(void* const* d_in, const int* in_sizes, int n_in,
                              void* d_out, int out_size) {
    const float* x      = (const float*)d_in[0];
    const float* bc     = (const float*)d_in[1];
    const float* mc     = (const float*)d_in[2];
    const float* acurv  = (const float*)d_in[3];
    const float* w_qkv  = (const float*)d_in[4];
    const float* w_ap   = (const float*)d_in[5];
    const float* b_ap   = (const float*)d_in[6];
    const float* w_me   = (const float*)d_in[7];
    const float* b_me   = (const float*)d_in[8];
    const float* w_ms   = (const float*)d_in[9];
    const float* b_ms   = (const float*)d_in[10];
    const float* lnw    = (const float*)d_in[11];
    const float* lnb    = (const float*)d_in[12];
    float* out = (float*)d_out;

    float *p_l1, *p_qkv, *p_o, *p_ap, *p_l2, *p_h, *p_hp, *p_m;
    cudaGetSymbolAddress((void**)&p_l1,  g_l1);
    cudaGetSymbolAddress((void**)&p_qkv, g_qkv);
    cudaGetSymbolAddress((void**)&p_o,   g_o);
    cudaGetSymbolAddress((void**)&p_ap,  g_ap);
    cudaGetSymbolAddress((void**)&p_l2,  g_l2);
    cudaGetSymbolAddress((void**)&p_h,   g_h);
    cudaGetSymbolAddress((void**)&p_hp,  g_hp);
    cudaGetSymbolAddress((void**)&p_m,   g_m);

    // 1. LN + project
    ln_project_kernel<<<MROWS, 256>>>(x, lnw, lnb, bc, p_l1);
    // 2. qkv = l1 @ w_qkv
    sgemm_kernel<<<dim3(QKVN / 128, MROWS / 128), 256>>>(p_l1, w_qkv, nullptr, p_qkv,
                                                         MROWS, QKVN, EP1);
    // 3. rope + norms
    rope_prep_kernel<<<(B_ * H_ * T_) / 8, 256>>>(acurv);
    // 4. attention
    attn_kernel<<<dim3(T_ / 128, B_ * H_), 128>>>(acurv);
    // 5. ap = o @ w_attn_proj + b
    sgemm_kernel<<<dim3(E_ / 128, MROWS / 128), 256>>>(p_o, w_ap, b_ap, p_ap,
                                                       MROWS, E_, AOW);
    // 6. y1 = x + ap; l2 = project(LN(y1))
    resid_ln_project_kernel<<<MROWS, 256>>>(x, lnw, lnb, bc);
    // 7. h = l2 @ w_mlp_expand + b
    sgemm_kernel<<<dim3((MEXP + 127) / 128, MROWS / 128), 256>>>(p_l2, w_me, b_me, p_h,
                                                                MROWS, MEXP, EP1);
    // 8. hp = project(gelu(h))
    gelu_project_kernel<<<MROWS, 256>>>(mc);
    // 9. m = hp @ w_mlp_shrink + b
    sgemm_kernel<<<dim3(E_ / 128, MROWS / 128), 256>>>(p_hp, w_ms, b_ms, p_m,
                                                       MROWS, E_, MSHK);
    // 10. out = project(y1 + m)
    final_project_kernel<<<MROWS, 256>>>(bc, out);
}

// round 4
// speedup vs baseline: 2.1231x; 2.1231x over previous
#include <cuda_runtime.h>
#include <math.h>
#include <stdint.h>

// Problem dims
#define B_  2
#define T_  2048
#define E_  1024
#define H_  16
#define D_  64
#define MROWS (B_*T_)            // 4096
#define QKVN  (3*E_)             // 3072
#define MEXP  4099               // 4E+3
// padded K dims for tensor-core GEMMs (multiples of 32)
#define KP1   1056               // pads 1025 and 1040
#define KP4   4128               // pads 4100
#define NP_ME 4224               // padded N for mlp expand (4099 -> 33*128)

// ---------------- scratch (static device globals; no allocation) -------------
__device__ float g_l1 [MROWS*KP1];
__device__ float g_qkv[MROWS*QKVN];
__device__ float g_Q  [B_*H_*T_*D_];
__device__ float g_Kr [B_*H_*T_*D_];
__device__ float g_qt [B_*H_*T_];
__device__ float g_kt [B_*H_*T_];
__device__ float g_v0 [B_*H_*T_];
__device__ float g_o  [MROWS*KP1];
__device__ float g_ap [MROWS*E_];
__device__ float g_y1 [MROWS*E_];
__device__ float g_l2 [MROWS*KP1];
__device__ float g_h  [MROWS*MEXP];
__device__ float g_hp [MROWS*KP4];
__device__ float g_m  [MROWS*E_];
// transposed + tf32-rounded + zero-padded weights: Wt[N,K]
__device__ float g_wt_qkv[QKVN*KP1];
__device__ float g_wt_ap [E_*KP1];
__device__ float g_wt_me [NP_ME*KP1];
__device__ float g_wt_ms [E_*KP4];

// ---------------- helpers -----------------------------------------------------
__device__ __forceinline__ uint32_t smem_u32(const void* p) {
    uint32_t a;
    asm("{ .reg .u64 t; cvta.to.shared.u64 t, %1; cvt.u32.u64 %0, t; }" : "=r"(a) : "l"(p));
    return a;
}
__device__ __forceinline__ float rna_tf32(float x) {
    uint32_t r;
    asm("cvt.rna.tf32.f32 %0, %1;" : "=r"(r) : "f"(x));
    return __uint_as_float(r);
}
#define CP_ASYNC16(dst, src) \
    asm volatile("cp.async.cg.shared.global [%0], [%1], 16;" :: "r"(dst), "l"(src))
#define CP_COMMIT()  asm volatile("cp.async.commit_group;")
#define CP_WAIT(n)   asm volatile("cp.async.wait_group %0;" :: "n"(n))

__device__ __forceinline__ void mma_tf32(float* c, const float* a, const float* b) {
    asm volatile(
        "mma.sync.aligned.m16n8k8.row.col.f32.tf32.tf32.f32 "
        "{%0,%1,%2,%3}, {%4,%5,%6,%7}, {%8,%9}, {%0,%1,%2,%3};"
        : "+f"(c[0]), "+f"(c[1]), "+f"(c[2]), "+f"(c[3])
        : "r"(__float_as_uint(a[0])), "r"(__float_as_uint(a[1])),
          "r"(__float_as_uint(a[2])), "r"(__float_as_uint(a[3])),
          "r"(__float_as_uint(b[0])), "r"(__float_as_uint(b[1])));
}

__device__ __forceinline__ float block_reduce_sum(float v, float* red) {
    int tid = threadIdx.x;
    #pragma unroll
    for (int o = 16; o; o >>= 1) v += __shfl_xor_sync(0xffffffffu, v, o);
    if ((tid & 31) == 0) red[tid >> 5] = v;
    __syncthreads();
    float r = (tid < (int)(blockDim.x >> 5)) ? red[tid] : 0.f;
    if (tid < 32) {
        #pragma unroll
        for (int o = 16; o; o >>= 1) r += __shfl_xor_sync(0xffffffffu, r, o);
        if (tid == 0) red[0] = r;
    }
    __syncthreads();
    float out = red[0];
    __syncthreads();
    return out;
}

// ---------------- weight transpose + tf32 round + zero pad -------------------
// W[K,N] row-major -> Wt[Npad rows, Kpad] (grid covers padded dims)
__global__ void transpose_round_kernel(const float* __restrict__ W,
                                       float* __restrict__ Wt,
                                       int K, int N, int Kpad) {
    __shared__ float s[32][33];
    int k0 = blockIdx.x * 32, n0 = blockIdx.y * 32;
    int tx = threadIdx.x, ty = threadIdx.y;          // 32 x 8
    #pragma unroll
    for (int yy = ty; yy < 32; yy += 8) {
        int k = k0 + yy, n = n0 + tx;
        float v = (k < K && n < N) ? W[(size_t)k * N + n] : 0.f;
        s[yy][tx] = rna_tf32(v);
    }
    __syncthreads();
    #pragma unroll
    for (int yy = ty; yy < 32; yy += 8) {
        int n = n0 + yy, k = k0 + tx;
        Wt[(size_t)n * Kpad + k] = s[tx][yy];
    }
}

// ---------------- tf32 tensor-core GEMM (mma.sync, baseline PTX) --------------
// C[M,N] = A[M,Kpad] @ Wt[N,Kpad]^T + bias. 128x128 tiles, BK=32, 8 warps.
// SMEM row stride 36 floats (16B-aligned, conflict-free fragment reads).
#define GSTRIDE 36
#define ABUF_F (128*GSTRIDE)     // 4608 floats per buffer
__global__ void __launch_bounds__(256, 1) gemm_tf32_kernel(
        const float* __restrict__ A, int lda,
        const float* __restrict__ Bt, int ldb,
        const float* __restrict__ bias,
        float* __restrict__ C, int ldc, int Nact, int nchunks) {
    extern __shared__ float sm[];
    uint32_t smaddr = smem_u32(sm);
    int tid = threadIdx.x;
    int lane = tid & 31, w = tid >> 5;
    int grp = lane >> 2, tig = lane & 3;
    int wm = w >> 1, wn = w & 1;                  // 4 x 2 warp grid
    int row0 = blockIdx.y * 128, col0 = blockIdx.x * 128;

    float acc[2][8][4];
    #pragma unroll
    for (int mi = 0; mi < 2; ++mi)
        #pragma unroll
        for (int ni = 0; ni < 8; ++ni)
            #pragma unroll
            for (int cc = 0; cc < 4; ++cc) acc[mi][ni][cc] = 0.f;

    const float* Arow = A  + (size_t)row0 * lda;
    const float* Brow = Bt + (size_t)col0 * ldb;

    auto load_chunk = [&](int buf, int kc) {
        int k0 = kc * 32;
        uint32_t abase = smaddr + buf * (ABUF_F * 4);
        uint32_t bbase = smaddr + 2 * (ABUF_F * 4) + buf * (ABUF_F * 4);
        #pragma unroll
        for (int u = 0; u < 4; ++u) {
            int idx = tid + u * 256;
            int r = idx >> 3, c = idx & 7;
            CP_ASYNC16(abase + r * (GSTRIDE * 4) + c * 16,
                       Arow + (size_t)r * lda + k0 + c * 4);
            CP_ASYNC16(bbase + r * (GSTRIDE * 4) + c * 16,
                       Brow + (size_t)r * ldb + k0 + c * 4);
        }
        CP_COMMIT();
    };

    load_chunk(0, 0);
    for (int i = 0; i < nchunks; ++i) {
        int buf = i & 1;
        if (i + 1 < nchunks) { load_chunk(buf ^ 1, i + 1); CP_WAIT(1); }
        else                 { CP_WAIT(0); }
        __syncthreads();
        const float* Asb = sm + buf * ABUF_F;
        const float* Bsb = sm + 2 * ABUF_F + buf * ABUF_F;
        #pragma unroll
        for (int ks = 0; ks < 4; ++ks) {
            int kk = ks * 8;
            float a[2][4];
            #pragma unroll
            for (int mi = 0; mi < 2; ++mi) {
                int ra = wm * 32 + mi * 16 + grp;
                a[mi][0] = Asb[ra * GSTRIDE + kk + tig];
                a[mi][1] = Asb[(ra + 8) * GSTRIDE + kk + tig];
                a[mi][2] = Asb[ra * GSTRIDE + kk + tig + 4];
                a[mi][3] = Asb[(ra + 8) * GSTRIDE + kk + tig + 4];
            }
            float b[8][2];
            #pragma unroll
            for (int ni = 0; ni < 8; ++ni) {
                int nb = wn * 64 + ni * 8 + grp;
                b[ni][0] = Bsb[nb * GSTRIDE + kk + tig];
                b[ni][1] = Bsb[nb * GSTRIDE + kk + tig + 4];
            }
            #pragma unroll
            for (int mi = 0; mi < 2; ++mi)
                #pragma unroll
                for (int ni = 0; ni < 8; ++ni)
                    mma_tf32(acc[mi][ni], a[mi], b[ni]);
        }
        __syncthreads();
    }

    // epilogue: direct stores (quad-contiguous 32B sectors)
    #pragma unroll
    for (int mi = 0; mi < 2; ++mi) {
        int rbase = row0 + wm * 32 + mi * 16 + grp;
        #pragma unroll
        for (int ni = 0; ni < 8; ++ni) {
            int gc = col0 + wn * 64 + ni * 8 + tig * 2;
            if (gc < Nact) {
                float b0 = bias ? bias[gc] : 0.f;
                float b1 = (bias && gc + 1 < Nact) ? bias[gc + 1] : 0.f;
                float* p0 = C + (size_t)rbase * ldc + gc;
                float* p1 = C + (size_t)(rbase + 8) * ldc + gc;
                p0[0] = acc[mi][ni][0] + b0;
                if (gc + 1 < Nact) p0[1] = acc[mi][ni][1] + b1;
                p1[0] = acc[mi][ni][2] + b0;
                if (gc + 1 < Nact) p1[1] = acc[mi][ni][3] + b1;
            }
        }
    }
}

// ---------------- kernel 1: LN + project of x -> l1 (M, KP1) ------------------
__global__ void ln_project_kernel(const float* __restrict__ x,
                                  const float* __restrict__ lnw,
                                  const float* __restrict__ lnb,
                                  const float* __restrict__ bc,
                                  float* __restrict__ out) {
    int row = blockIdx.x;
    int tid = threadIdx.x;
    const float* xr = x + (size_t)row * E_;
    __shared__ float red[32];
    float loc[4];
    float s = 0.f;
    #pragma unroll
    for (int u = 0; u < 4; ++u) { loc[u] = xr[tid + u * 256]; s += loc[u]; }
    float mean = block_reduce_sum(s, red) * (1.0f / E_);
    float vs = 0.f;
    #pragma unroll
    for (int u = 0; u < 4; ++u) { float d = loc[u] - mean; vs += d * d; }
    float var = block_reduce_sum(vs, red) * (1.0f / E_);
    float rstd = rsqrtf(var + 1e-5f);
    float Kb = expf(bc[0]);
    float ss = 0.f;
    float* orow = out + (size_t)row * KP1;
    #pragma unroll
    for (int u = 0; u < 4; ++u) {
        int c = tid + u * 256;
        float y = (loc[u] - mean) * rstd * lnw[c] + lnb[c];
        orow[1 + c] = rna_tf32(y);
        ss += y * y;
    }
    float sst = block_reduce_sum(ss, red);
    if (tid == 0) orow[0] = rna_tf32(sqrtf(Kb + sst));
    if (tid < 31) orow[1025 + tid] = 0.f;       // pad to KP1
}

// ---------------- kernel 3: RoPE + per-head norms ----------------------------
__global__ void rope_prep_kernel(const float* __restrict__ curv) {
    int tid = threadIdx.x;
    int lane = tid & 31;
    int rsub = tid >> 5;
    int r = blockIdx.x * 8 + rsub;            // r = bh*T + t
    int bh = r >> 11;
    int t  = r & (T_ - 1);
    int b  = bh >> 4;
    int h  = bh & 15;
    float Ka = expf(curv[h]);
    size_t base = ((size_t)(b * T_ + t)) * QKVN + h * D_;
    float q1 = g_qkv[base + lane],        q2 = g_qkv[base + 32 + lane];
    float k1 = g_qkv[base + E_ + lane],   k2 = g_qkv[base + E_ + 32 + lane];
    float v1 = g_qkv[base + 2*E_ + lane], v2 = g_qkv[base + 2*E_ + 32 + lane];
    float inv = powf(10000.0f, -(float)lane * (1.0f / 32.0f));
    float fr = (float)t * inv;
    float sn, cs;
    sincosf(fr, &sn, &cs);
    float qa = q1 * cs + q2 * sn, qb = -q1 * sn + q2 * cs;
    float ka = k1 * cs + k2 * sn, kb = -k1 * sn + k2 * cs;
    float sq = qa * qa + qb * qb;
    float sk = ka * ka + kb * kb;
    float sv = v1 * v1 + v2 * v2;
    #pragma unroll
    for (int o = 16; o; o >>= 1) {
        sq += __shfl_xor_sync(0xffffffffu, sq, o);
        sk += __shfl_xor_sync(0xffffffffu, sk, o);
        sv += __shfl_xor_sync(0xffffffffu, sv, o);
    }
    size_t ob = ((size_t)bh * T_ + t) * D_;
    g_Q[ob + lane] = qa;  g_Q[ob + 32 + lane] = qb;
    g_Kr[ob + lane] = ka; g_Kr[ob + 32 + lane] = kb;
    if (lane == 0) {
        g_qt[r] = sqrtf(Ka + sq);
        g_kt[r] = sqrtf(Ka + sk);
        g_v0[r] = sqrtf(Ka + sv);
    }
}

// ---------------- kernel 4: hyperbolic causal attention ----------------------
__global__ void __launch_bounds__(128) attn_kernel(const float* __restrict__ curv) {
    int bh = blockIdx.y;
    int b = bh >> 4, h = bh & 15;
    int q0 = blockIdx.x * 128;
    int tid = threadIdx.x;
    int qi = q0 + tid;
    float Ka = expf(curv[h]);
    float sK = sqrtf(Ka);
    float rKa = 1.0f / Ka;

    __shared__ float ksh[32 * 64];
    __shared__ float vsh[32 * 64];
    __shared__ float kts[32], v0s[32];

    float q[64];
    {
        const float4* Qb = (const float4*)(g_Q + ((size_t)bh * T_ + qi) * D_);
        #pragma unroll
        for (int d4 = 0; d4 < 16; ++d4) {
            float4 f = Qb[d4];
            q[4*d4] = f.x; q[4*d4+1] = f.y; q[4*d4+2] = f.z; q[4*d4+3] = f.w;
        }
    }
    float myqt = g_qt[(size_t)bh * T_ + qi];
    float o[65];
    #pragma unroll
    for (int e = 0; e < 65; ++e) o[e] = 0.f;
    float ssum = 0.f;

    int kend = q0 + 128;
    for (int k0 = 0; k0 < kend; k0 += 32) {
        __syncthreads();
        #pragma unroll
        for (int u = 0; u < 4; ++u) {
            int idx = tid + u * 128;           // float4 index
            int r = idx >> 4, d4 = idx & 15;
            ((float4*)ksh)[idx] =
                ((const float4*)(g_Kr + ((size_t)bh * T_ + k0 + r) * D_))[d4];
            ((float4*)vsh)[idx] =
                ((const float4*)(g_qkv + ((size_t)(b * T_ + k0 + r)) * QKVN + 2*E_ + h * D_))[d4];
        }
        if (tid < 32) {
            kts[tid] = g_kt[(size_t)bh * T_ + k0 + tid];
            v0s[tid] = g_v0[(size_t)bh * T_ + k0 + tid];
        }
        __syncthreads();
        if (qi >= k0) {
            int nk = min(32, qi - k0 + 1);
            for (int j = 0; j < nk; ++j) {
                const float4* kr4 = (const float4*)(ksh + j * 64);
                float d0 = 0.f, d1 = 0.f, d2 = 0.f, d3 = 0.f;
                #pragma unroll
                for (int d4 = 0; d4 < 16; ++d4) {
                    float4 kf = kr4[d4];
                    d0 += q[4*d4]   * kf.x;
                    d1 += q[4*d4+1] * kf.y;
                    d2 += q[4*d4+2] * kf.z;
                    d3 += q[4*d4+3] * kf.w;
                }
                float inner = (d0 + d1) + (d2 + d3) - myqt * kts[j];
                float ratio = fmaxf(-inner * rKa, 1.0f + 1e-7f);
                // exp(-sK*acosh(r)) via fast MUFU: acosh(r)=log(r+sqrt((r-1)(r+1)))
                float rm1 = ratio - 1.0f;
                float arg = ratio + sqrtf(rm1 * (ratio + 1.0f));
                float p = __expf(-sK * __logf(arg));
                ssum += p;
                o[0] += p * v0s[j];
                const float4* vr4 = (const float4*)(vsh + j * 64);
                #pragma unroll
                for (int d4 = 0; d4 < 16; ++d4) {
                    float4 vf = vr4[d4];
                    o[1 + 4*d4]     += p * vf.x;
                    o[1 + 4*d4 + 1] += p * vf.y;
                    o[1 + 4*d4 + 2] += p * vf.z;
                    o[1 + 4*d4 + 3] += p * vf.w;
                }
            }
        }
    }
    float rs = 1.0f / ssum;
    #pragma unroll
    for (int e = 0; e < 65; ++e) o[e] *= rs;
    float s2 = 0.f;
    #pragma unroll
    for (int d = 0; d < 64; ++d) s2 += o[1 + d] * o[1 + d];
    float ln2 = o[0] * o[0] - s2;
    float hn = sqrtf(fmaxf(ln2, 1e-12f));
    float sc = sK / hn;
    float* ob = g_o + ((size_t)(b * T_ + qi)) * KP1 + h * 65;
    #pragma unroll
    for (int e = 0; e < 65; ++e) ob[e] = rna_tf32(o[e] * sc);
    if (h == 15) {                            // pad cols 1040..1055 of this row
        float* pr = g_o + ((size_t)(b * T_ + qi)) * KP1;
        #pragma unroll
        for (int i = 0; i < 16; ++i) pr[1040 + i] = 0.f;
    }
}

// ---------------- kernel 6: residual + LN + project -> y1, l2 ----------------
__global__ void resid_ln_project_kernel(const float* __restrict__ x,
                                        const float* __restrict__ lnw,
                                        const float* __restrict__ lnb,
                                        const float* __restrict__ bc) {
    int row = blockIdx.x;
    int tid = threadIdx.x;
    const float* xr = x + (size_t)row * E_;
    const float* ar = g_ap + (size_t)row * E_;
    float* yr = g_y1 + (size_t)row * E_;
    __shared__ float red[32];
    float loc[4];
    float s = 0.f;
    #pragma unroll
    for (int u = 0; u < 4; ++u) {
        int c = tid + u * 256;
        float y = xr[c] + ar[c];
        yr[c] = y;
        loc[u] = y;
        s += y;
    }
    float mean = block_reduce_sum(s, red) * (1.0f / E_);
    float vs = 0.f;
    #pragma unroll
    for (int u = 0; u < 4; ++u) { float d = loc[u] - mean; vs += d * d; }
    float var = block_reduce_sum(vs, red) * (1.0f / E_);
    float rstd = rsqrtf(var + 1e-5f);
    float Kb = expf(bc[0]);
    float ss = 0.f;
    float* orow = g_l2 + (size_t)row * KP1;
    #pragma unroll
    for (int u = 0; u < 4; ++u) {
        int c = tid + u * 256;
        float y = (loc[u] - mean) * rstd * lnw[c] + lnb[c];
        orow[1 + c] = rna_tf32(y);
        ss += y * y;
    }
    float sst = block_reduce_sum(ss, red);
    if (tid == 0) orow[0] = rna_tf32(sqrtf(Kb + sst));
    if (tid < 31) orow[1025 + tid] = 0.f;
}

// ---------------- kernel 8: exact GELU + project (mlp curvature) -------------
__global__ void gelu_project_kernel(const float* __restrict__ mc) {
    int row = blockIdx.x;
    int tid = threadIdx.x;
    const float* hr = g_h + (size_t)row * MEXP;
    float* op = g_hp + (size_t)row * KP4;
    __shared__ float red[32];
    float Km = expf(mc[0]);
    float ss = 0.f;
    for (int c = tid; c < MEXP; c += 256) {
        float v = hr[c];
        float g = 0.5f * v * (1.0f + erff(v * 0.70710678118654752f));
        op[1 + c] = rna_tf32(g);
        ss += g * g;
    }
    float sst = block_reduce_sum(ss, red);
    if (tid == 0) op[0] = rna_tf32(sqrtf(Km + sst));
    if (tid < 28) op[4100 + tid] = 0.f;       // pad to KP4
}

// ---------------- kernel 10: final residual + project -> out -----------------
__global__ void final_project_kernel(const float* __restrict__ bc,
                                     float* __restrict__ out) {
    int row = blockIdx.x;
    int tid = threadIdx.x;
    const float* yr = g_y1 + (size_t)row * E_;
    const float* mr = g_m + (size_t)row * E_;
    float* orow = out + (size_t)row * (E_ + 1);
    __shared__ float red[32];
    float Kb = expf(bc[0]);
    float ss = 0.f;
    #pragma unroll
    for (int u = 0; u < 4; ++u) {
        int c = tid + u * 256;
        float y = yr[c] + mr[c];
        orow[1 + c] = y;
        ss += y * y;
    }
    float sst = block_reduce_sum(ss, red);
    if (tid == 0) orow[0] = sqrtf(Kb + sst);
}

// ---------------- launch -----------------------------------------------------
extern "C" void kernel_launch(void* const* d_in, const int* in_sizes, int n_in,
                              void* d_out, int out_size) {
    const float* x      = (const float*)d_in[0];
    const float* bc     = (const float*)d_in[1];
    const float* mc     = (const float*)d_in[2];
    const float* acurv  = (const float*)d_in[3];
    const float* w_qkv  = (const float*)d_in[4];
    const float* w_ap   = (const float*)d_in[5];
    const float* b_ap   = (const float*)d_in[6];
    const float* w_me   = (const float*)d_in[7];
    const float* b_me   = (const float*)d_in[8];
    const float* w_ms   = (const float*)d_in[9];
    const float* b_ms   = (const float*)d_in[10];
    const float* lnw    = (const float*)d_in[11];
    const float* lnb    = (const float*)d_in[12];
    float* out = (float*)d_out;

    float *p_l1, *p_qkv, *p_o, *p_ap, *p_l2, *p_h, *p_hp, *p_m;
    float *p_wq, *p_wa, *p_we, *p_ws;
    cudaGetSymbolAddress((void**)&p_l1,  g_l1);
    cudaGetSymbolAddress((void**)&p_qkv, g_qkv);
    cudaGetSymbolAddress((void**)&p_o,   g_o);
    cudaGetSymbolAddress((void**)&p_ap,  g_ap);
    cudaGetSymbolAddress((void**)&p_l2,  g_l2);
    cudaGetSymbolAddress((void**)&p_h,   g_h);
    cudaGetSymbolAddress((void**)&p_hp,  g_hp);
    cudaGetSymbolAddress((void**)&p_m,   g_m);
    cudaGetSymbolAddress((void**)&p_wq,  g_wt_qkv);
    cudaGetSymbolAddress((void**)&p_wa,  g_wt_ap);
    cudaGetSymbolAddress((void**)&p_we,  g_wt_me);
    cudaGetSymbolAddress((void**)&p_ws,  g_wt_ms);

    const int GSMEM = 4 * ABUF_F * 4;   // 73728 bytes
    cudaFuncSetAttribute(gemm_tf32_kernel,
                         cudaFuncAttributeMaxDynamicSharedMemorySize, GSMEM);

    dim3 tb(32, 8);
    // weight transposes (tf32-rounded, zero-padded)
    transpose_round_kernel<<<dim3(KP1/32, QKVN/32), tb>>>(w_qkv, p_wq, 1025, 3072, KP1);
    transpose_round_kernel<<<dim3(KP1/32, E_/32),   tb>>>(w_ap,  p_wa, 1040, 1024, KP1);
    transpose_round_kernel<<<dim3(KP1/32, NP_ME/32),tb>>>(w_me,  p_we, 1025, 4099, KP1);
    transpose_round_kernel<<<dim3(KP4/32, E_/32),   tb>>>(w_ms,  p_ws, 4100, 1024, KP4);

    // 1. LN + project
    ln_project_kernel<<<MROWS, 256>>>(x, lnw, lnb, bc, p_l1);
    // 2. qkv = l1 @ w_qkv               (M=4096, N=3072, K=1025)
    gemm_tf32_kernel<<<dim3(QKVN/128, MROWS/128), 256, GSMEM>>>(
        p_l1, KP1, p_wq, KP1, nullptr, p_qkv, QKVN, QKVN, KP1/32);
    // 3. rope + norms
    rope_prep_kernel<<<(B_ * H_ * T_) / 8, 256>>>(acurv);
    // 4. attention
    attn_kernel<<<dim3(T_ / 128, B_ * H_), 128>>>(acurv);
    // 5. ap = o @ w_attn_proj + b       (M=4096, N=1024, K=1040)
    gemm_tf32_kernel<<<dim3(E_/128, MROWS/128), 256, GSMEM>>>(
        p_o, KP1, p_wa, KP1, b_ap, p_ap, E_, E_, KP1/32);
    // 6. y1 = x + ap; l2 = project(LN(y1))
    resid_ln_project_kernel<<<MROWS, 256>>>(x, lnw, lnb, bc);
    // 7. h = l2 @ w_mlp_expand + b      (M=4096, N=4099, K=1025)
    gemm_tf32_kernel<<<dim3(NP_ME/128, MROWS/128), 256, GSMEM>>>(
        p_l2, KP1, p_we, KP1, b_me, p_h, MEXP, MEXP, KP1/32);
    // 8. hp = project(gelu(h))
    gelu_project_kernel<<<MROWS, 256>>>(mc);
    // 9. m = hp @ w_mlp_shrink + b      (M=4096, N=1024, K=4100)
    gemm_tf32_kernel<<<dim3(E_/128, MROWS/128), 256, GSMEM>>>(
        p_hp, KP4, p_ws, KP4, b_ms, p_m, E_, E_, KP4/32);
    // 10. out = project(y1 + m)
    final_project_kernel<<<MROWS, 256>>>(bc, out);
}

// round 5
// speedup vs baseline: 2.6045x; 1.2267x over previous
#include <cuda_runtime.h>
#include <math.h>
#include <stdint.h>

// Problem dims
#define B_  2
#define T_  2048
#define E_  1024
#define H_  16
#define D_  64
#define MROWS (B_*T_)            // 4096
#define QKVN  (3*E_)             // 3072
#define MEXP  4099               // 4E+3
// padded K dims for tensor-core GEMMs (multiples of 32)
#define KP1   1056               // pads 1025 and 1040
#define KP4   4128               // pads 4100
#define NP_ME 4224               // padded N for mlp expand (4099 -> 33*128)

// ---------------- scratch (static device globals; no allocation) -------------
__device__ float g_l1 [MROWS*KP1];
__device__ float g_qkv[MROWS*QKVN];
__device__ float g_Q  [B_*H_*T_*D_];
__device__ float g_Kr [B_*H_*T_*D_];
__device__ float g_V  [B_*H_*T_*D_];
__device__ float g_qt [B_*H_*T_];
__device__ float g_kt [B_*H_*T_];
__device__ float g_v0 [B_*H_*T_];
__device__ float g_o  [MROWS*KP1];
__device__ float g_ap [MROWS*E_];
__device__ float g_y1 [MROWS*E_];
__device__ float g_l2 [MROWS*KP1];
__device__ float g_h  [MROWS*MEXP];
__device__ float g_hp [MROWS*KP4];
__device__ float g_m  [MROWS*E_];
// transposed + tf32-rounded + zero-padded weights: Wt[N,K]
__device__ float g_wt_qkv[QKVN*KP1];
__device__ float g_wt_ap [E_*KP1];
__device__ float g_wt_me [NP_ME*KP1];
__device__ float g_wt_ms [E_*KP4];

// ---------------- helpers -----------------------------------------------------
__device__ __forceinline__ uint32_t smem_u32(const void* p) {
    uint32_t a;
    asm("{ .reg .u64 t; cvta.to.shared.u64 t, %1; cvt.u32.u64 %0, t; }" : "=r"(a) : "l"(p));
    return a;
}
__device__ __forceinline__ float rna_tf32(float x) {
    uint32_t r;
    asm("cvt.rna.tf32.f32 %0, %1;" : "=r"(r) : "f"(x));
    return __uint_as_float(r);
}
#define CP_ASYNC16(dst, src) \
    asm volatile("cp.async.cg.shared.global [%0], [%1], 16;" :: "r"(dst), "l"(src))
#define CP_COMMIT()  asm volatile("cp.async.commit_group;")
#define CP_WAIT(n)   asm volatile("cp.async.wait_group %0;" :: "n"(n))

__device__ __forceinline__ void mma_tf32(float* c, const float* a, const float* b) {
    asm volatile(
        "mma.sync.aligned.m16n8k8.row.col.f32.tf32.tf32.f32 "
        "{%0,%1,%2,%3}, {%4,%5,%6,%7}, {%8,%9}, {%0,%1,%2,%3};"
        : "+f"(c[0]), "+f"(c[1]), "+f"(c[2]), "+f"(c[3])
        : "r"(__float_as_uint(a[0])), "r"(__float_as_uint(a[1])),
          "r"(__float_as_uint(a[2])), "r"(__float_as_uint(a[3])),
          "r"(__float_as_uint(b[0])), "r"(__float_as_uint(b[1])));
}

__device__ __forceinline__ float block_reduce_sum(float v, float* red) {
    int tid = threadIdx.x;
    #pragma unroll
    for (int o = 16; o; o >>= 1) v += __shfl_xor_sync(0xffffffffu, v, o);
    if ((tid & 31) == 0) red[tid >> 5] = v;
    __syncthreads();
    float r = (tid < (int)(blockDim.x >> 5)) ? red[tid] : 0.f;
    if (tid < 32) {
        #pragma unroll
        for (int o = 16; o; o >>= 1) r += __shfl_xor_sync(0xffffffffu, r, o);
        if (tid == 0) red[0] = r;
    }
    __syncthreads();
    float out = red[0];
    __syncthreads();
    return out;
}

// ---------------- weight transpose + tf32 round + zero pad -------------------
__global__ void transpose_round_kernel(const float* __restrict__ W,
                                       float* __restrict__ Wt,
                                       int K, int N, int Kpad) {
    __shared__ float s[32][33];
    int k0 = blockIdx.x * 32, n0 = blockIdx.y * 32;
    int tx = threadIdx.x, ty = threadIdx.y;          // 32 x 8
    #pragma unroll
    for (int yy = ty; yy < 32; yy += 8) {
        int k = k0 + yy, n = n0 + tx;
        float v = (k < K && n < N) ? W[(size_t)k * N + n] : 0.f;
        s[yy][tx] = rna_tf32(v);
    }
    __syncthreads();
    #pragma unroll
    for (int yy = ty; yy < 32; yy += 8) {
        int n = n0 + yy, k = k0 + tx;
        Wt[(size_t)n * Kpad + k] = s[tx][yy];
    }
}

// ---------------- tf32 tensor-core GEMM (mma.sync) ----------------------------
#define GSTRIDE 36
#define ABUF_F (128*GSTRIDE)
__global__ void __launch_bounds__(256, 1) gemm_tf32_kernel(
        const float* __restrict__ A, int lda,
        const float* __restrict__ Bt, int ldb,
        const float* __restrict__ bias,
        float* __restrict__ C, int ldc, int Nact, int nchunks) {
    extern __shared__ float sm[];
    uint32_t smaddr = smem_u32(sm);
    int tid = threadIdx.x;
    int lane = tid & 31, w = tid >> 5;
    int grp = lane >> 2, tig = lane & 3;
    int wm = w >> 1, wn = w & 1;
    int row0 = blockIdx.y * 128, col0 = blockIdx.x * 128;

    float acc[2][8][4];
    #pragma unroll
    for (int mi = 0; mi < 2; ++mi)
        #pragma unroll
        for (int ni = 0; ni < 8; ++ni)
            #pragma unroll
            for (int cc = 0; cc < 4; ++cc) acc[mi][ni][cc] = 0.f;

    const float* Arow = A  + (size_t)row0 * lda;
    const float* Brow = Bt + (size_t)col0 * ldb;

    auto load_chunk = [&](int buf, int kc) {
        int k0 = kc * 32;
        uint32_t abase = smaddr + buf * (ABUF_F * 4);
        uint32_t bbase = smaddr + 2 * (ABUF_F * 4) + buf * (ABUF_F * 4);
        #pragma unroll
        for (int u = 0; u < 4; ++u) {
            int idx = tid + u * 256;
            int r = idx >> 3, c = idx & 7;
            CP_ASYNC16(abase + r * (GSTRIDE * 4) + c * 16,
                       Arow + (size_t)r * lda + k0 + c * 4);
            CP_ASYNC16(bbase + r * (GSTRIDE * 4) + c * 16,
                       Brow + (size_t)r * ldb + k0 + c * 4);
        }
        CP_COMMIT();
    };

    load_chunk(0, 0);
    for (int i = 0; i < nchunks; ++i) {
        int buf = i & 1;
        if (i + 1 < nchunks) { load_chunk(buf ^ 1, i + 1); CP_WAIT(1); }
        else                 { CP_WAIT(0); }
        __syncthreads();
        const float* Asb = sm + buf * ABUF_F;
        const float* Bsb = sm + 2 * ABUF_F + buf * ABUF_F;
        #pragma unroll
        for (int ks = 0; ks < 4; ++ks) {
            int kk = ks * 8;
            float a[2][4];
            #pragma unroll
            for (int mi = 0; mi < 2; ++mi) {
                int ra = wm * 32 + mi * 16 + grp;
                a[mi][0] = Asb[ra * GSTRIDE + kk + tig];
                a[mi][1] = Asb[(ra + 8) * GSTRIDE + kk + tig];
                a[mi][2] = Asb[ra * GSTRIDE + kk + tig + 4];
                a[mi][3] = Asb[(ra + 8) * GSTRIDE + kk + tig + 4];
            }
            float b[8][2];
            #pragma unroll
            for (int ni = 0; ni < 8; ++ni) {
                int nb = wn * 64 + ni * 8 + grp;
                b[ni][0] = Bsb[nb * GSTRIDE + kk + tig];
                b[ni][1] = Bsb[nb * GSTRIDE + kk + tig + 4];
            }
            #pragma unroll
            for (int mi = 0; mi < 2; ++mi)
                #pragma unroll
                for (int ni = 0; ni < 8; ++ni)
                    mma_tf32(acc[mi][ni], a[mi], b[ni]);
        }
        __syncthreads();
    }

    #pragma unroll
    for (int mi = 0; mi < 2; ++mi) {
        int rbase = row0 + wm * 32 + mi * 16 + grp;
        #pragma unroll
        for (int ni = 0; ni < 8; ++ni) {
            int gc = col0 + wn * 64 + ni * 8 + tig * 2;
            if (gc < Nact) {
                float b0 = bias ? bias[gc] : 0.f;
                float b1 = (bias && gc + 1 < Nact) ? bias[gc + 1] : 0.f;
                float* p0 = C + (size_t)rbase * ldc + gc;
                float* p1 = C + (size_t)(rbase + 8) * ldc + gc;
                p0[0] = acc[mi][ni][0] + b0;
                if (gc + 1 < Nact) p0[1] = acc[mi][ni][1] + b1;
                p1[0] = acc[mi][ni][2] + b0;
                if (gc + 1 < Nact) p1[1] = acc[mi][ni][3] + b1;
            }
        }
    }
}

// ---------------- kernel 1: LN + project of x -> l1 (M, KP1) ------------------
__global__ void ln_project_kernel(const float* __restrict__ x,
                                  const float* __restrict__ lnw,
                                  const float* __restrict__ lnb,
                                  const float* __restrict__ bc,
                                  float* __restrict__ out) {
    int row = blockIdx.x;
    int tid = threadIdx.x;
    const float* xr = x + (size_t)row * E_;
    __shared__ float red[32];
    float loc[4];
    float s = 0.f;
    #pragma unroll
    for (int u = 0; u < 4; ++u) { loc[u] = xr[tid + u * 256]; s += loc[u]; }
    float mean = block_reduce_sum(s, red) * (1.0f / E_);
    float vs = 0.f;
    #pragma unroll
    for (int u = 0; u < 4; ++u) { float d = loc[u] - mean; vs += d * d; }
    float var = block_reduce_sum(vs, red) * (1.0f / E_);
    float rstd = rsqrtf(var + 1e-5f);
    float Kb = expf(bc[0]);
    float ss = 0.f;
    float* orow = out + (size_t)row * KP1;
    #pragma unroll
    for (int u = 0; u < 4; ++u) {
        int c = tid + u * 256;
        float y = (loc[u] - mean) * rstd * lnw[c] + lnb[c];
        orow[1 + c] = rna_tf32(y);
        ss += y * y;
    }
    float sst = block_reduce_sum(ss, red);
    if (tid == 0) orow[0] = rna_tf32(sqrtf(Kb + sst));
    if (tid < 31) orow[1025 + tid] = 0.f;
}

// ---------------- kernel 3: RoPE + per-head norms (tf32-consistent) ----------
__global__ void rope_prep_kernel(const float* __restrict__ curv) {
    int tid = threadIdx.x;
    int lane = tid & 31;
    int rsub = tid >> 5;
    int r = blockIdx.x * 8 + rsub;            // r = bh*T + t
    int bh = r >> 11;
    int t  = r & (T_ - 1);
    int b  = bh >> 4;
    int h  = bh & 15;
    float Ka = expf(curv[h]);
    size_t base = ((size_t)(b * T_ + t)) * QKVN + h * D_;
    float q1 = g_qkv[base + lane],        q2 = g_qkv[base + 32 + lane];
    float k1 = g_qkv[base + E_ + lane],   k2 = g_qkv[base + E_ + 32 + lane];
    float v1 = g_qkv[base + 2*E_ + lane], v2 = g_qkv[base + 2*E_ + 32 + lane];
    float inv = powf(10000.0f, -(float)lane * (1.0f / 32.0f));
    float fr = (float)t * inv;
    float sn, cs;
    sincosf(fr, &sn, &cs);
    // round to tf32 BEFORE norms so mma dot products stay consistent with qt/kt/v0
    float qa = rna_tf32(q1 * cs + q2 * sn), qb = rna_tf32(-q1 * sn + q2 * cs);
    float ka = rna_tf32(k1 * cs + k2 * sn), kb = rna_tf32(-k1 * sn + k2 * cs);
    float va = rna_tf32(v1),                vb = rna_tf32(v2);
    float sq = qa * qa + qb * qb;
    float sk = ka * ka + kb * kb;
    float sv = va * va + vb * vb;
    #pragma unroll
    for (int o = 16; o; o >>= 1) {
        sq += __shfl_xor_sync(0xffffffffu, sq, o);
        sk += __shfl_xor_sync(0xffffffffu, sk, o);
        sv += __shfl_xor_sync(0xffffffffu, sv, o);
    }
    size_t ob = ((size_t)bh * T_ + t) * D_;
    g_Q[ob + lane] = qa;  g_Q[ob + 32 + lane] = qb;
    g_Kr[ob + lane] = ka; g_Kr[ob + 32 + lane] = kb;
    g_V[ob + lane] = va;  g_V[ob + 32 + lane] = vb;
    if (lane == 0) {
        g_qt[r] = sqrtf(Ka + sq);
        g_kt[r] = sqrtf(Ka + sk);
        g_v0[r] = sqrtf(Ka + sv);
    }
}

// ---------------- kernel 4: hyperbolic causal attention (tensor-core) --------
// CTA = 128 queries x one (b,h). 8 warps, each warp owns 16 query rows.
// S = Q K^T via tf32 mma; transcendental in regs; P staged via SMEM (same-warp
// rows -> __syncwarp only); O = P V via tf32 mma.
#define KSTR 68
#define PSTR 36
__global__ void __launch_bounds__(256, 1) attn_kernel(const float* __restrict__ curv) {
    __shared__ float ksh[32 * KSTR];
    __shared__ float vsh[32 * KSTR];
    __shared__ float psh[128 * PSTR];
    __shared__ float kts[32], v0s[32];

    int bh = blockIdx.y;
    int b = bh >> 4, h = bh & 15;
    int q0 = blockIdx.x * 128;
    int tid = threadIdx.x, lane = tid & 31, w = tid >> 5;
    int grp = lane >> 2, tig = lane & 3;
    float Ka = expf(curv[h]);
    float sK = sqrtf(Ka);
    float rKa = 1.0f / Ka;
    float nsK = -sK;

    int r0 = q0 + w * 16 + grp;     // query rows owned by this thread
    int r1 = r0 + 8;
    int rowlo = w * 16 + grp;       // local row in psh

    // Q fragments (register-resident for the whole CTA)
    float qf[8][4];
    {
        const float* Q0 = g_Q + ((size_t)bh * T_ + r0) * D_;
        const float* Q1 = g_Q + ((size_t)bh * T_ + r1) * D_;
        #pragma unroll
        for (int ks = 0; ks < 8; ++ks) {
            qf[ks][0] = Q0[8 * ks + tig];
            qf[ks][1] = Q1[8 * ks + tig];
            qf[ks][2] = Q0[8 * ks + tig + 4];
            qf[ks][3] = Q1[8 * ks + tig + 4];
        }
    }
    float qt0 = g_qt[(size_t)bh * T_ + r0];
    float qt1 = g_qt[(size_t)bh * T_ + r1];

    float oacc[8][4];
    #pragma unroll
    for (int nb = 0; nb < 8; ++nb)
        #pragma unroll
        for (int cc = 0; cc < 4; ++cc) oacc[nb][cc] = 0.f;
    float ssum0 = 0.f, ssum1 = 0.f, o00 = 0.f, o01 = 0.f;

    for (int k0 = 0; k0 < q0 + 128; k0 += 32) {
        __syncthreads();
        // load K/V tiles (32 rows x 64 d) + norms
        for (int u = tid; u < 512; u += 256) {
            int rr = u >> 4, d4 = u & 15;
            *(float4*)&ksh[rr * KSTR + d4 * 4] =
                *(const float4*)(g_Kr + ((size_t)bh * T_ + k0 + rr) * D_ + d4 * 4);
            *(float4*)&vsh[rr * KSTR + d4 * 4] =
                *(const float4*)(g_V + ((size_t)bh * T_ + k0 + rr) * D_ + d4 * 4);
        }
        if (tid < 32) {
            kts[tid] = g_kt[(size_t)bh * T_ + k0 + tid];
            v0s[tid] = g_v0[(size_t)bh * T_ + k0 + tid];
        }
        __syncthreads();
        if (q0 + w * 16 + 15 < k0) continue;    // warp fully masked

        // ---- S = Q K^T (16x32 per warp) ----
        float sacc[4][4];
        #pragma unroll
        for (int nb = 0; nb < 4; ++nb)
            #pragma unroll
            for (int cc = 0; cc < 4; ++cc) sacc[nb][cc] = 0.f;
        #pragma unroll
        for (int ks = 0; ks < 8; ++ks) {
            float bb[4][2];
            #pragma unroll
            for (int nb = 0; nb < 4; ++nb) {
                bb[nb][0] = ksh[(nb * 8 + grp) * KSTR + 8 * ks + tig];
                bb[nb][1] = ksh[(nb * 8 + grp) * KSTR + 8 * ks + tig + 4];
            }
            #pragma unroll
            for (int nb = 0; nb < 4; ++nb)
                mma_tf32(sacc[nb], qf[ks], bb[nb]);
        }

        // ---- scores -> p ----
        #pragma unroll
        for (int nb = 0; nb < 4; ++nb) {
            int cl = nb * 8 + 2 * tig;
            float ktc0 = kts[cl], ktc1 = kts[cl + 1];
            float v0c0 = v0s[cl], v0c1 = v0s[cl + 1];
            int cg0 = k0 + cl, cg1 = cg0 + 1;
            float p0, p1, p2, p3;
            {
                float ratio = fmaxf(-(sacc[nb][0] - qt0 * ktc0) * rKa, 1.0f + 1e-7f);
                float arg = ratio + sqrtf((ratio - 1.f) * (ratio + 1.f));
                p0 = (cg0 <= r0) ? rna_tf32(__expf(nsK * __logf(arg))) : 0.f;
            }
            {
                float ratio = fmaxf(-(sacc[nb][1] - qt0 * ktc1) * rKa, 1.0f + 1e-7f);
                float arg = ratio + sqrtf((ratio - 1.f) * (ratio + 1.f));
                p1 = (cg1 <= r0) ? rna_tf32(__expf(nsK * __logf(arg))) : 0.f;
            }
            {
                float ratio = fmaxf(-(sacc[nb][2] - qt1 * ktc0) * rKa, 1.0f + 1e-7f);
                float arg = ratio + sqrtf((ratio - 1.f) * (ratio + 1.f));
                p2 = (cg0 <= r1) ? rna_tf32(__expf(nsK * __logf(arg))) : 0.f;
            }
            {
                float ratio = fmaxf(-(sacc[nb][3] - qt1 * ktc1) * rKa, 1.0f + 1e-7f);
                float arg = ratio + sqrtf((ratio - 1.f) * (ratio + 1.f));
                p3 = (cg1 <= r1) ? rna_tf32(__expf(nsK * __logf(arg))) : 0.f;
            }
            ssum0 += p0 + p1;  o00 += p0 * v0c0 + p1 * v0c1;
            ssum1 += p2 + p3;  o01 += p2 * v0c0 + p3 * v0c1;
            *(float2*)&psh[rowlo * PSTR + cl]       = make_float2(p0, p1);
            *(float2*)&psh[(rowlo + 8) * PSTR + cl] = make_float2(p2, p3);
        }
        __syncwarp();

        // ---- O += P V (16x64 per warp) ----
        #pragma unroll
        for (int ks = 0; ks < 4; ++ks) {
            float af[4];
            af[0] = psh[rowlo * PSTR + 8 * ks + tig];
            af[1] = psh[(rowlo + 8) * PSTR + 8 * ks + tig];
            af[2] = psh[rowlo * PSTR + 8 * ks + tig + 4];
            af[3] = psh[(rowlo + 8) * PSTR + 8 * ks + tig + 4];
            #pragma unroll
            for (int nb = 0; nb < 8; ++nb) {
                float bb[2];
                bb[0] = vsh[(8 * ks + tig) * KSTR + nb * 8 + grp];
                bb[1] = vsh[(8 * ks + tig + 4) * KSTR + nb * 8 + grp];
                mma_tf32(oacc[nb], af, bb);
            }
        }
        __syncwarp();
    }

    // quad reductions (lanes differing in tig bits)
    #pragma unroll
    for (int m = 1; m < 4; m <<= 1) {
        ssum0 += __shfl_xor_sync(0xffffffffu, ssum0, m);
        ssum1 += __shfl_xor_sync(0xffffffffu, ssum1, m);
        o00   += __shfl_xor_sync(0xffffffffu, o00, m);
        o01   += __shfl_xor_sync(0xffffffffu, o01, m);
    }
    float rs0 = 1.0f / ssum0, rs1 = 1.0f / ssum1;
    float on0 = o00 * rs0, on1 = o01 * rs1;
    float s20 = 0.f, s21 = 0.f;
    #pragma unroll
    for (int nb = 0; nb < 8; ++nb) {
        float a0 = oacc[nb][0] * rs0, a1 = oacc[nb][1] * rs0;
        float a2 = oacc[nb][2] * rs1, a3 = oacc[nb][3] * rs1;
        oacc[nb][0] = a0; oacc[nb][1] = a1; oacc[nb][2] = a2; oacc[nb][3] = a3;
        s20 += a0 * a0 + a1 * a1;
        s21 += a2 * a2 + a3 * a3;
    }
    #pragma unroll
    for (int m = 1; m < 4; m <<= 1) {
        s20 += __shfl_xor_sync(0xffffffffu, s20, m);
        s21 += __shfl_xor_sync(0xffffffffu, s21, m);
    }
    float hn0 = sqrtf(fmaxf(on0 * on0 - s20, 1e-12f));
    float hn1 = sqrtf(fmaxf(on1 * on1 - s21, 1e-12f));
    float sc0 = sK / hn0, sc1 = sK / hn1;

    float* base0 = g_o + ((size_t)(b * T_ + r0)) * KP1 + h * 65;
    float* base1 = g_o + ((size_t)(b * T_ + r1)) * KP1 + h * 65;
    if (tig == 0) {
        base0[0] = rna_tf32(on0 * sc0);
        base1[0] = rna_tf32(on1 * sc1);
    }
    #pragma unroll
    for (int nb = 0; nb < 8; ++nb) {
        int c = nb * 8 + 2 * tig;
        base0[1 + c]     = rna_tf32(oacc[nb][0] * sc0);
        base0[1 + c + 1] = rna_tf32(oacc[nb][1] * sc0);
        base1[1 + c]     = rna_tf32(oacc[nb][2] * sc1);
        base1[1 + c + 1] = rna_tf32(oacc[nb][3] * sc1);
    }
    if (h == 15) {                  // zero pad cols 1040..1055
        float* pr0 = g_o + ((size_t)(b * T_ + r0)) * KP1;
        float* pr1 = g_o + ((size_t)(b * T_ + r1)) * KP1;
        #pragma unroll
        for (int i = 0; i < 4; ++i) {
            pr0[1040 + tig * 4 + i] = 0.f;
            pr1[1040 + tig * 4 + i] = 0.f;
        }
    }
}

// ---------------- kernel 6: residual + LN + project -> y1, l2 ----------------
__global__ void resid_ln_project_kernel(const float* __restrict__ x,
                                        const float* __restrict__ lnw,
                                        const float* __restrict__ lnb,
                                        const float* __restrict__ bc) {
    int row = blockIdx.x;
    int tid = threadIdx.x;
    const float* xr = x + (size_t)row * E_;
    const float* ar = g_ap + (size_t)row * E_;
    float* yr = g_y1 + (size_t)row * E_;
    __shared__ float red[32];
    float loc[4];
    float s = 0.f;
    #pragma unroll
    for (int u = 0; u < 4; ++u) {
        int c = tid + u * 256;
        float y = xr[c] + ar[c];
        yr[c] = y;
        loc[u] = y;
        s += y;
    }
    float mean = block_reduce_sum(s, red) * (1.0f / E_);
    float vs = 0.f;
    #pragma unroll
    for (int u = 0; u < 4; ++u) { float d = loc[u] - mean; vs += d * d; }
    float var = block_reduce_sum(vs, red) * (1.0f / E_);
    float rstd = rsqrtf(var + 1e-5f);
    float Kb = expf(bc[0]);
    float ss = 0.f;
    float* orow = g_l2 + (size_t)row * KP1;
    #pragma unroll
    for (int u = 0; u < 4; ++u) {
        int c = tid + u * 256;
        float y = (loc[u] - mean) * rstd * lnw[c] + lnb[c];
        orow[1 + c] = rna_tf32(y);
        ss += y * y;
    }
    float sst = block_reduce_sum(ss, red);
    if (tid == 0) orow[0] = rna_tf32(sqrtf(Kb + sst));
    if (tid < 31) orow[1025 + tid] = 0.f;
}

// ---------------- kernel 8: exact GELU + project (mlp curvature) -------------
__global__ void gelu_project_kernel(const float* __restrict__ mc) {
    int row = blockIdx.x;
    int tid = threadIdx.x;
    const float* hr = g_h + (size_t)row * MEXP;
    float* op = g_hp + (size_t)row * KP4;
    __shared__ float red[32];
    float Km = expf(mc[0]);
    float ss = 0.f;
    for (int c = tid; c < MEXP; c += 256) {
        float v = hr[c];
        float g = 0.5f * v * (1.0f + erff(v * 0.70710678118654752f));
        op[1 + c] = rna_tf32(g);
        ss += g * g;
    }
    float sst = block_reduce_sum(ss, red);
    if (tid == 0) op[0] = rna_tf32(sqrtf(Km + sst));
    if (tid < 28) op[4100 + tid] = 0.f;
}

// ---------------- kernel 10: final residual + project -> out -----------------
__global__ void final_project_kernel(const float* __restrict__ bc,
                                     float* __restrict__ out) {
    int row = blockIdx.x;
    int tid = threadIdx.x;
    const float* yr = g_y1 + (size_t)row * E_;
    const float* mr = g_m + (size_t)row * E_;
    float* orow = out + (size_t)row * (E_ + 1);
    __shared__ float red[32];
    float Kb = expf(bc[0]);
    float ss = 0.f;
    #pragma unroll
    for (int u = 0; u < 4; ++u) {
        int c = tid + u * 256;
        float y = yr[c] + mr[c];
        orow[1 + c] = y;
        ss += y * y;
    }
    float sst = block_reduce_sum(ss, red);
    if (tid == 0) orow[0] = sqrtf(Kb + sst);
}

// ---------------- launch -----------------------------------------------------
extern "C" void kernel_launch(void* const* d_in, const int* in_sizes, int n_in,
                              void* d_out, int out_size) {
    const float* x      = (const float*)d_in[0];
    const float* bc     = (const float*)d_in[1];
    const float* mc     = (const float*)d_in[2];
    const float* acurv  = (const float*)d_in[3];
    const float* w_qkv  = (const float*)d_in[4];
    const float* w_ap   = (const float*)d_in[5];
    const float* b_ap   = (const float*)d_in[6];
    const float* w_me   = (const float*)d_in[7];
    const float* b_me   = (const float*)d_in[8];
    const float* w_ms   = (const float*)d_in[9];
    const float* b_ms   = (const float*)d_in[10];
    const float* lnw    = (const float*)d_in[11];
    const float* lnb    = (const float*)d_in[12];
    float* out = (float*)d_out;

    float *p_l1, *p_qkv, *p_o, *p_ap, *p_l2, *p_h, *p_hp, *p_m;
    float *p_wq, *p_wa, *p_we, *p_ws;
    cudaGetSymbolAddress((void**)&p_l1,  g_l1);
    cudaGetSymbolAddress((void**)&p_qkv, g_qkv);
    cudaGetSymbolAddress((void**)&p_o,   g_o);
    cudaGetSymbolAddress((void**)&p_ap,  g_ap);
    cudaGetSymbolAddress((void**)&p_l2,  g_l2);
    cudaGetSymbolAddress((void**)&p_h,   g_h);
    cudaGetSymbolAddress((void**)&p_hp,  g_hp);
    cudaGetSymbolAddress((void**)&p_m,   g_m);
    cudaGetSymbolAddress((void**)&p_wq,  g_wt_qkv);
    cudaGetSymbolAddress((void**)&p_wa,  g_wt_ap);
    cudaGetSymbolAddress((void**)&p_we,  g_wt_me);
    cudaGetSymbolAddress((void**)&p_ws,  g_wt_ms);

    const int GSMEM = 4 * ABUF_F * 4;   // 73728 bytes
    cudaFuncSetAttribute(gemm_tf32_kernel,
                         cudaFuncAttributeMaxDynamicSharedMemorySize, GSMEM);

    dim3 tb(32, 8);
    transpose_round_kernel<<<dim3(KP1/32, QKVN/32), tb>>>(w_qkv, p_wq, 1025, 3072, KP1);
    transpose_round_kernel<<<dim3(KP1/32, E_/32),   tb>>>(w_ap,  p_wa, 1040, 1024, KP1);
    transpose_round_kernel<<<dim3(KP1/32, NP_ME/32),tb>>>(w_me,  p_we, 1025, 4099, KP1);
    transpose_round_kernel<<<dim3(KP4/32, E_/32),   tb>>>(w_ms,  p_ws, 4100, 1024, KP4);

    ln_project_kernel<<<MROWS, 256>>>(x, lnw, lnb, bc, p_l1);
    gemm_tf32_kernel<<<dim3(QKVN/128, MROWS/128), 256, GSMEM>>>(
        p_l1, KP1, p_wq, KP1, nullptr, p_qkv, QKVN, QKVN, KP1/32);
    rope_prep_kernel<<<(B_ * H_ * T_) / 8, 256>>>(acurv);
    attn_kernel<<<dim3(T_ / 128, B_ * H_), 256>>>(acurv);
    gemm_tf32_kernel<<<dim3(E_/128, MROWS/128), 256, GSMEM>>>(
        p_o, KP1, p_wa, KP1, b_ap, p_ap, E_, E_, KP1/32);
    resid_ln_project_kernel<<<MROWS, 256>>>(x, lnw, lnb, bc);
    gemm_tf32_kernel<<<dim3(NP_ME/128, MROWS/128), 256, GSMEM>>>(
        p_l2, KP1, p_we, KP1, b_me, p_h, MEXP, MEXP, KP1/32);
    gelu_project_kernel<<<MROWS, 256>>>(mc);
    gemm_tf32_kernel<<<dim3(E_/128, MROWS/128), 256, GSMEM>>>(
        p_hp, KP4, p_ws, KP4, b_ms, p_m, E_, E_, KP4/32);
    final_project_kernel<<<MROWS, 256>>>(bc, out);
}